// round 3
// baseline (speedup 1.0000x reference)
#include <cuda_runtime.h>
#include <cuda_bf16.h>
#include <cstddef>

// Problem constants
#define BB   64
#define TT   2048
#define HH   128
#define GG   384     // 3*H
#define DIN  18
#define DOUT 2
#define BTR  (BB*TT)           // 131072 rows
#define GK   256               // layer-1 input width

typedef unsigned long long u64;

// ---------------------------------------------------------------------------
// Scratch (device globals; no allocation allowed)
// ---------------------------------------------------------------------------
static __device__ float g_xgF[(size_t)BTR * GG];   // 201 MB
static __device__ float g_xgR[(size_t)BTR * GG];   // 201 MB
static __device__ float g_h  [(size_t)BTR * 2*HH]; // 134 MB (h0, then reused for h1)

// ---------------------------------------------------------------------------
// Helpers
// ---------------------------------------------------------------------------
__device__ __forceinline__ u64 ffma2(u64 a, u64 b, u64 c) {
    u64 d;
    asm("fma.rn.f32x2 %0, %1, %2, %3;" : "=l"(d) : "l"(a), "l"(b), "l"(c));
    return d;
}
__device__ __forceinline__ u64 d2u(double x) {
    return (u64)__double_as_longlong(x);
}
__device__ __forceinline__ u64 pack2(float a) {     // (a, a) pair
    u64 d;
    asm("mov.b64 %0, {%1, %1};" : "=l"(d) : "f"(a));
    return d;
}
__device__ __forceinline__ float2 unpack2(u64 v) {
    float2 r;
    asm("mov.b64 {%0, %1}, %2;" : "=f"(r.x), "=f"(r.y) : "l"(v));
    return r;
}
__device__ __forceinline__ float sigf(float x) {
    return 1.0f / (1.0f + __expf(-x));
}
__device__ __forceinline__ float tanh_fast(float x) {
    float xc = fminf(fmaxf(x, -20.0f), 20.0f);
    float e  = __expf(-2.0f * xc);
    return (1.0f - e) / (1.0f + e);
}

// ---------------------------------------------------------------------------
// Generic fp32 GEMM (K=18 projections): C[M][N] = A[M][K]*B[N][K]^T + bias[N]
// ---------------------------------------------------------------------------
__global__ __launch_bounds__(256) void gemm_tn_bias(
    const float* __restrict__ A, int lda,
    const float* __restrict__ Bw,
    const float* __restrict__ bias,
    float* __restrict__ C, int ldc,
    int M, int N, int K)
{
    const int BM = 64, BN = 64, BK = 16;
    const int PAD = 8;
    __shared__ __align__(16) float As[BK][BM + PAD];
    __shared__ __align__(16) float Bs[BK][BN + PAD];

    int tid = threadIdx.x;
    int tx = tid & 15;
    int ty = tid >> 4;
    int m0 = blockIdx.x * BM;
    int n0 = blockIdx.y * BN;

    float acc[4][4];
#pragma unroll
    for (int i = 0; i < 4; i++)
#pragma unroll
        for (int j = 0; j < 4; j++) acc[i][j] = 0.0f;

    int nkt = (K + BK - 1) / BK;
    for (int kt = 0; kt < nkt; kt++) {
        int k0 = kt * BK;
#pragma unroll
        for (int r = 0; r < 4; r++) {
            int idx = tid + r * 256;
            int m = idx >> 4;
            int k = idx & 15;
            float va = 0.0f, vb = 0.0f;
            if (k0 + k < K) {
                va = A[(size_t)(m0 + m) * lda + k0 + k];
                vb = Bw[(size_t)(n0 + m) * K + k0 + k];
            }
            As[k][m] = va;
            Bs[k][m] = vb;
        }
        __syncthreads();
#pragma unroll
        for (int k = 0; k < BK; k++) {
            float4 a = *(const float4*)&As[k][ty * 4];
            float4 b = *(const float4*)&Bs[k][tx * 4];
            float av[4] = {a.x, a.y, a.z, a.w};
            float bv[4] = {b.x, b.y, b.z, b.w};
#pragma unroll
            for (int i = 0; i < 4; i++)
#pragma unroll
                for (int j = 0; j < 4; j++)
                    acc[i][j] = fmaf(av[i], bv[j], acc[i][j]);
        }
        __syncthreads();
    }

#pragma unroll
    for (int i = 0; i < 4; i++) {
        int m = m0 + ty * 4 + i;
#pragma unroll
        for (int j = 0; j < 4; j++) {
            int n = n0 + tx * 4 + j;
            C[(size_t)m * ldc + n] = acc[i][j] + bias[n];
        }
    }
}

// ---------------------------------------------------------------------------
// K=256 GEMM with FFMA2:  C[BTR][384] = A[BTR][256]*Bw[384][256]^T + bias
// 128x128 tile, BK=16, 256 threads, 8x8 micro-tile.
// A stored NATURAL in smem; (a,a) pairs built in registers (mov.b64, alu pipe).
// B read as natural n-adjacent bit-packed pairs. acc pairs span n.
// ---------------------------------------------------------------------------
__global__ __launch_bounds__(256, 2) void gemm128(
    const float* __restrict__ A,      // [BTR][256]
    const float* __restrict__ Bw,     // [384][256]
    const float* __restrict__ bias,   // [384]
    float* __restrict__ C)            // [BTR][384]
{
    __shared__ __align__(16) float As[16][132];   // row 528B, 16B-aligned
    __shared__ __align__(16) float Bs[16][132];

    int tid = threadIdx.x;
    int tx = tid & 15;           // n group
    int ty = tid >> 4;           // m group
    int m0 = blockIdx.x * 128;
    int n0 = blockIdx.y * 128;

    u64 acc[8][4];
#pragma unroll
    for (int i = 0; i < 8; i++)
#pragma unroll
        for (int j = 0; j < 4; j++) acc[i][j] = 0ull;

    float bias_r[8];
#pragma unroll
    for (int j = 0; j < 8; j++) bias_r[j] = bias[n0 + tx * 8 + j];

    int rowA = tid >> 2;          // 0..63
    int kq   = (tid & 3) * 4;     // 0,4,8,12

    for (int k0 = 0; k0 < GK; k0 += 16) {
#pragma unroll
        for (int p = 0; p < 2; p++) {
            int r = rowA + p * 64;
            float4 a = *(const float4*)&A [(size_t)(m0 + r) * GK + k0 + kq];
            float4 b = *(const float4*)&Bw[(size_t)(n0 + r) * GK + k0 + kq];
            As[kq + 0][r] = a.x;
            As[kq + 1][r] = a.y;
            As[kq + 2][r] = a.z;
            As[kq + 3][r] = a.w;
            Bs[kq + 0][r] = b.x;
            Bs[kq + 1][r] = b.y;
            Bs[kq + 2][r] = b.z;
            Bs[kq + 3][r] = b.w;
        }
        __syncthreads();
#pragma unroll
        for (int k = 0; k < 16; k++) {
            float4 av0 = *(const float4*)&As[k][ty * 8];
            float4 av1 = *(const float4*)&As[k][ty * 8 + 4];
            double2 bp0 = *(const double2*)&Bs[k][tx * 8];
            double2 bp1 = *(const double2*)&Bs[k][tx * 8 + 4];
            u64 bb[4] = {d2u(bp0.x), d2u(bp0.y), d2u(bp1.x), d2u(bp1.y)};
            u64 aa[8] = {pack2(av0.x), pack2(av0.y), pack2(av0.z), pack2(av0.w),
                         pack2(av1.x), pack2(av1.y), pack2(av1.z), pack2(av1.w)};
#pragma unroll
            for (int i = 0; i < 8; i++)
#pragma unroll
                for (int j = 0; j < 4; j++)
                    acc[i][j] = ffma2(aa[i], bb[j], acc[i][j]);
        }
        __syncthreads();
    }

#pragma unroll
    for (int i = 0; i < 8; i++) {
        int m = m0 + ty * 8 + i;
        float2 p0 = unpack2(acc[i][0]);
        float2 p1 = unpack2(acc[i][1]);
        float2 p2 = unpack2(acc[i][2]);
        float2 p3 = unpack2(acc[i][3]);
        float4 o0 = make_float4(p0.x + bias_r[0], p0.y + bias_r[1],
                                p1.x + bias_r[2], p1.y + bias_r[3]);
        float4 o1 = make_float4(p2.x + bias_r[4], p2.y + bias_r[5],
                                p3.x + bias_r[6], p3.y + bias_r[7]);
        float* crow = &C[(size_t)m * GG + n0 + tx * 8];
        *(float4*)(crow)     = o0;
        *(float4*)(crow + 4) = o1;
    }
}

// ---------------------------------------------------------------------------
// Dual-stream GRU scan: each block runs TWO batches of the SAME direction,
// sharing the register-resident w_hh. grid = 64: dir = bx&1, bpair = bx>>1.
// 384 threads; thread g computes gate g's matvec for both streams.
// Gate phase: threads [0,128) handle stream 0, [128,256) handle stream 1.
// ---------------------------------------------------------------------------
__global__ __launch_bounds__(384, 1) void gru_scan2(
    const float* __restrict__ xgF, const float* __restrict__ xgR,
    const float* __restrict__ whhF, const float* __restrict__ bhhF,
    const float* __restrict__ whhR, const float* __restrict__ bhhR,
    float* __restrict__ out)
{
    int dir = blockIdx.x & 1;
    int bp  = blockIdx.x >> 1;
    const float* xg  = dir ? xgR  : xgF;
    const float* whh = dir ? whhR : whhF;
    const float* bhh = dir ? bhhR : bhhF;

    int g   = threadIdx.x;
    int sid = g >> 7;        // 0,1 -> gate-phase stream; 2 -> matvec only
    int j   = g & 127;

    // Register-resident packed weight row: 64 pairs
    u64 w2[64];
    {
        const double2* wrow = (const double2*)(whh + (size_t)g * HH);
#pragma unroll
        for (int i = 0; i < 32; i++) {
            double2 v = wrow[i];
            w2[2*i+0] = d2u(v.x);
            w2[2*i+1] = d2u(v.y);
        }
    }
    float bh = bhh[g];

    __shared__ __align__(16) float hs[2][HH];
    __shared__ float gh[2][GG];
    if (g < 2 * HH) hs[g >> 7][g & 127] = 0.0f;

    // Per-thread stream pointers (valid when sid < 2)
    int mybatch = 2 * bp + (sid < 2 ? sid : 0);
    const float* myXG  = xg + (size_t)mybatch * TT * GG;
    float*       myOut = out + (size_t)mybatch * TT * (2*HH) + (size_t)dir * HH + j;

    // Prefetch first step
    float xr = 0.f, xz = 0.f, xn = 0.f;
    {
        int tt0 = dir ? (TT - 1) : 0;
        if (sid < 2) {
            const float* p = myXG + (size_t)tt0 * GG;
            xr = p[j]; xz = p[j + HH]; xn = p[j + 2*HH];
        }
    }
    __syncthreads();

    const double2* h0d = (const double2*)hs[0];
    const double2* h1d = (const double2*)hs[1];

    for (int t = 0; t < TT; t++) {
        int tt = dir ? (TT - 1 - t) : t;

        // Prefetch next step
        float nxr = 0.f, nxz = 0.f, nxn = 0.f;
        if (sid < 2 && t + 1 < TT) {
            int tn = dir ? (tt - 1) : (tt + 1);
            const float* p = myXG + (size_t)tn * GG;
            nxr = p[j]; nxz = p[j + HH]; nxn = p[j + 2*HH];
        }

        // Matvec for both streams: 128 FFMA2 per thread
        u64 a00 = 0ull, a01 = 0ull, a10 = 0ull, a11 = 0ull;
#pragma unroll
        for (int i = 0; i < 32; i++) {
            double2 q0 = h0d[i];
            double2 q1 = h1d[i];
            u64 wA = w2[2*i], wB = w2[2*i+1];
            a00 = ffma2(wA, d2u(q0.x), a00);
            a01 = ffma2(wB, d2u(q0.y), a01);
            a10 = ffma2(wA, d2u(q1.x), a10);
            a11 = ffma2(wB, d2u(q1.y), a11);
        }
        {
            float2 p0 = unpack2(a00), p1 = unpack2(a01);
            float2 p2 = unpack2(a10), p3 = unpack2(a11);
            gh[0][g] = ((p0.x + p0.y) + (p1.x + p1.y)) + bh;
            gh[1][g] = ((p2.x + p2.y) + (p3.x + p3.y)) + bh;
        }
        __syncthreads();

        if (sid < 2) {
            float r  = sigf(xr + gh[sid][j]);
            float z  = sigf(xz + gh[sid][j + HH]);
            float n  = tanh_fast(xn + r * gh[sid][j + 2*HH]);
            float hp = hs[sid][j];
            float hn = fmaf(z, hp - n, n);   // (1-z)*n + z*h
            hs[sid][j] = hn;
            myOut[(size_t)tt * (2*HH)] = hn;
        }
        __syncthreads();

        xr = nxr; xz = nxz; xn = nxn;
    }
}

// ---------------------------------------------------------------------------
// Final FC
// ---------------------------------------------------------------------------
__global__ __launch_bounds__(256) void fc_kernel(
    const float* __restrict__ h,
    const float* __restrict__ fw,   // [2][256]
    const float* __restrict__ fb,   // [2]
    float* __restrict__ out)        // [rows][2]
{
    int row  = blockIdx.x * 8 + (threadIdx.x >> 5);
    int lane = threadIdx.x & 31;
    const float* hp = h + (size_t)row * (2*HH);
    float a0 = 0.f, a1 = 0.f;
#pragma unroll
    for (int i = 0; i < 8; i++) {
        int k = lane + 32 * i;
        float v = hp[k];
        a0 = fmaf(v, fw[k],       a0);
        a1 = fmaf(v, fw[256 + k], a1);
    }
#pragma unroll
    for (int off = 16; off; off >>= 1) {
        a0 += __shfl_xor_sync(0xffffffffu, a0, off);
        a1 += __shfl_xor_sync(0xffffffffu, a1, off);
    }
    if (lane == 0) {
        out[(size_t)row * 2 + 0] = a0 + fb[0];
        out[(size_t)row * 2 + 1] = a1 + fb[1];
    }
}

// ---------------------------------------------------------------------------
// Launch
// ---------------------------------------------------------------------------
extern "C" void kernel_launch(void* const* d_in, const int* in_sizes, int n_in,
                              void* d_out, int out_size)
{
    const float* x        = (const float*)d_in[0];
    const float* w_ih_l0  = (const float*)d_in[1];
    const float* w_hh_l0  = (const float*)d_in[2];
    const float* b_ih_l0  = (const float*)d_in[3];
    const float* b_hh_l0  = (const float*)d_in[4];
    const float* w_ih_l0r = (const float*)d_in[5];
    const float* w_hh_l0r = (const float*)d_in[6];
    const float* b_ih_l0r = (const float*)d_in[7];
    const float* b_hh_l0r = (const float*)d_in[8];
    const float* w_ih_l1  = (const float*)d_in[9];
    const float* w_hh_l1  = (const float*)d_in[10];
    const float* b_ih_l1  = (const float*)d_in[11];
    const float* b_hh_l1  = (const float*)d_in[12];
    const float* w_ih_l1r = (const float*)d_in[13];
    const float* w_hh_l1r = (const float*)d_in[14];
    const float* b_ih_l1r = (const float*)d_in[15];
    const float* b_hh_l1r = (const float*)d_in[16];
    const float* fc_w     = (const float*)d_in[17];
    const float* fc_b     = (const float*)d_in[18];
    float* out = (float*)d_out;

    float *xgF, *xgR, *hbuf;
    cudaGetSymbolAddress((void**)&xgF,  g_xgF);
    cudaGetSymbolAddress((void**)&xgR,  g_xgR);
    cudaGetSymbolAddress((void**)&hbuf, g_h);

    // Layer 0 input projections (K = 18)
    dim3 gGrid(BTR / 64, GG / 64);
    gemm_tn_bias<<<gGrid, 256>>>(x, DIN, w_ih_l0,  b_ih_l0,  xgF, GG, BTR, GG, DIN);
    gemm_tn_bias<<<gGrid, 256>>>(x, DIN, w_ih_l0r, b_ih_l0r, xgR, GG, BTR, GG, DIN);

    // Layer 0 scan (dual-stream blocks)
    gru_scan2<<<BB, GG>>>(xgF, xgR, w_hh_l0, b_hh_l0, w_hh_l0r, b_hh_l0r, hbuf);

    // Layer 1 input projections (K = 256)
    dim3 g2Grid(BTR / 128, GG / 128);
    gemm128<<<g2Grid, 256>>>(hbuf, w_ih_l1,  b_ih_l1,  xgF);
    gemm128<<<g2Grid, 256>>>(hbuf, w_ih_l1r, b_ih_l1r, xgR);

    // Layer 1 scan
    gru_scan2<<<BB, GG>>>(xgF, xgR, w_hh_l1, b_hh_l1, w_hh_l1r, b_hh_l1r, hbuf);

    // Final FC
    fc_kernel<<<BTR / 8, 256>>>(hbuf, fc_w, fc_b, out);
}

// round 4
// speedup vs baseline: 1.3913x; 1.3913x over previous
#include <cuda_runtime.h>
#include <cuda_bf16.h>
#include <cstddef>

// Problem constants
#define BB   64
#define TT   2048
#define HH   128
#define GG   384     // 3*H
#define DIN  18
#define DOUT 2
#define BTR  (BB*TT)           // 131072 rows
#define GK   256               // layer-1 input width

typedef unsigned long long u64;

// ---------------------------------------------------------------------------
// Scratch (device globals; no allocation allowed)
// ---------------------------------------------------------------------------
static __device__ float g_xgF[(size_t)BTR * GG];   // 201 MB
static __device__ float g_xgR[(size_t)BTR * GG];   // 201 MB
static __device__ float g_h  [(size_t)BTR * 2*HH]; // 134 MB (h0, then reused for h1)

// ---------------------------------------------------------------------------
// Helpers
// ---------------------------------------------------------------------------
__device__ __forceinline__ u64 ffma2(u64 a, u64 b, u64 c) {
    u64 d;
    asm("fma.rn.f32x2 %0, %1, %2, %3;" : "=l"(d) : "l"(a), "l"(b), "l"(c));
    return d;
}
__device__ __forceinline__ u64 d2u(double x) {
    return (u64)__double_as_longlong(x);
}
__device__ __forceinline__ u64 pack2(float a) {     // (a, a) pair
    u64 d;
    asm("mov.b64 %0, {%1, %1};" : "=l"(d) : "f"(a));
    return d;
}
__device__ __forceinline__ float2 unpack2(u64 v) {
    float2 r;
    asm("mov.b64 {%0, %1}, %2;" : "=f"(r.x), "=f"(r.y) : "l"(v));
    return r;
}
__device__ __forceinline__ float sigf(float x) {
    return 1.0f / (1.0f + __expf(-x));
}
__device__ __forceinline__ float tanh_fast(float x) {
    float xc = fminf(fmaxf(x, -20.0f), 20.0f);
    float e  = __expf(-2.0f * xc);
    return (1.0f - e) / (1.0f + e);
}

// ---------------------------------------------------------------------------
// Generic fp32 GEMM (K=18 projections): C[M][N] = A[M][K]*B[N][K]^T + bias[N]
// 64x64 tile, BK=16, 256 threads, 4x4 micro-tile, float4 epilogue stores.
// ---------------------------------------------------------------------------
__global__ __launch_bounds__(256) void gemm_tn_bias(
    const float* __restrict__ A, int lda,
    const float* __restrict__ Bw,
    const float* __restrict__ bias,
    float* __restrict__ C, int ldc,
    int M, int N, int K)
{
    const int BM = 64, BN = 64, BK = 16;
    const int PAD = 8;
    __shared__ __align__(16) float As[BK][BM + PAD];
    __shared__ __align__(16) float Bs[BK][BN + PAD];

    int tid = threadIdx.x;
    int tx = tid & 15;
    int ty = tid >> 4;
    int m0 = blockIdx.x * BM;
    int n0 = blockIdx.y * BN;

    float acc[4][4];
#pragma unroll
    for (int i = 0; i < 4; i++)
#pragma unroll
        for (int j = 0; j < 4; j++) acc[i][j] = 0.0f;

    int nkt = (K + BK - 1) / BK;
    for (int kt = 0; kt < nkt; kt++) {
        int k0 = kt * BK;
#pragma unroll
        for (int r = 0; r < 4; r++) {
            int idx = tid + r * 256;
            int m = idx >> 4;
            int k = idx & 15;
            float va = 0.0f, vb = 0.0f;
            if (k0 + k < K) {
                va = A[(size_t)(m0 + m) * lda + k0 + k];
                vb = Bw[(size_t)(n0 + m) * K + k0 + k];
            }
            As[k][m] = va;
            Bs[k][m] = vb;
        }
        __syncthreads();
#pragma unroll
        for (int k = 0; k < BK; k++) {
            float4 a = *(const float4*)&As[k][ty * 4];
            float4 b = *(const float4*)&Bs[k][tx * 4];
            float av[4] = {a.x, a.y, a.z, a.w};
            float bv[4] = {b.x, b.y, b.z, b.w};
#pragma unroll
            for (int i = 0; i < 4; i++)
#pragma unroll
                for (int j = 0; j < 4; j++)
                    acc[i][j] = fmaf(av[i], bv[j], acc[i][j]);
        }
        __syncthreads();
    }

    float4 bv = *(const float4*)&bias[n0 + tx * 4];
#pragma unroll
    for (int i = 0; i < 4; i++) {
        int m = m0 + ty * 4 + i;
        float4 o = make_float4(acc[i][0] + bv.x, acc[i][1] + bv.y,
                               acc[i][2] + bv.z, acc[i][3] + bv.w);
        *(float4*)&C[(size_t)m * ldc + n0 + tx * 4] = o;
    }
}

// ---------------------------------------------------------------------------
// K=256 GEMM with FFMA2 (at SIMT issue floor):
// C[BTR][384] = A[BTR][256]*Bw[384][256]^T + bias
// 128x128 tile, BK=16, 256 threads, 8x8 micro-tile.
// ---------------------------------------------------------------------------
__global__ __launch_bounds__(256, 2) void gemm128(
    const float* __restrict__ A,      // [BTR][256]
    const float* __restrict__ Bw,     // [384][256]
    const float* __restrict__ bias,   // [384]
    float* __restrict__ C)            // [BTR][384]
{
    __shared__ __align__(16) float As[16][132];
    __shared__ __align__(16) float Bs[16][132];

    int tid = threadIdx.x;
    int tx = tid & 15;           // n group
    int ty = tid >> 4;           // m group
    int m0 = blockIdx.x * 128;
    int n0 = blockIdx.y * 128;

    u64 acc[8][4];
#pragma unroll
    for (int i = 0; i < 8; i++)
#pragma unroll
        for (int j = 0; j < 4; j++) acc[i][j] = 0ull;

    float bias_r[8];
#pragma unroll
    for (int j = 0; j < 8; j++) bias_r[j] = bias[n0 + tx * 8 + j];

    int rowA = tid >> 2;          // 0..63
    int kq   = (tid & 3) * 4;     // 0,4,8,12

    for (int k0 = 0; k0 < GK; k0 += 16) {
#pragma unroll
        for (int p = 0; p < 2; p++) {
            int r = rowA + p * 64;
            float4 a = *(const float4*)&A [(size_t)(m0 + r) * GK + k0 + kq];
            float4 b = *(const float4*)&Bw[(size_t)(n0 + r) * GK + k0 + kq];
            As[kq + 0][r] = a.x;
            As[kq + 1][r] = a.y;
            As[kq + 2][r] = a.z;
            As[kq + 3][r] = a.w;
            Bs[kq + 0][r] = b.x;
            Bs[kq + 1][r] = b.y;
            Bs[kq + 2][r] = b.z;
            Bs[kq + 3][r] = b.w;
        }
        __syncthreads();
#pragma unroll
        for (int k = 0; k < 16; k++) {
            float4 av0 = *(const float4*)&As[k][ty * 8];
            float4 av1 = *(const float4*)&As[k][ty * 8 + 4];
            double2 bp0 = *(const double2*)&Bs[k][tx * 8];
            double2 bp1 = *(const double2*)&Bs[k][tx * 8 + 4];
            u64 bb[4] = {d2u(bp0.x), d2u(bp0.y), d2u(bp1.x), d2u(bp1.y)};
            u64 aa[8] = {pack2(av0.x), pack2(av0.y), pack2(av0.z), pack2(av0.w),
                         pack2(av1.x), pack2(av1.y), pack2(av1.z), pack2(av1.w)};
#pragma unroll
            for (int i = 0; i < 8; i++)
#pragma unroll
                for (int j = 0; j < 4; j++)
                    acc[i][j] = ffma2(aa[i], bb[j], acc[i][j]);
        }
        __syncthreads();
    }

#pragma unroll
    for (int i = 0; i < 8; i++) {
        int m = m0 + ty * 8 + i;
        float2 p0 = unpack2(acc[i][0]);
        float2 p1 = unpack2(acc[i][1]);
        float2 p2 = unpack2(acc[i][2]);
        float2 p3 = unpack2(acc[i][3]);
        float4 o0 = make_float4(p0.x + bias_r[0], p0.y + bias_r[1],
                                p1.x + bias_r[2], p1.y + bias_r[3]);
        float4 o1 = make_float4(p2.x + bias_r[4], p2.y + bias_r[5],
                                p3.x + bias_r[6], p3.y + bias_r[7]);
        float* crow = &C[(size_t)m * GG + n0 + tx * 8];
        *(float4*)(crow)     = o0;
        *(float4*)(crow + 4) = o1;
    }
}

// ---------------------------------------------------------------------------
// GRU scan (R2 layout: one block per (batch, dir), full SM parallelism).
// grid = 128 blocks, 384 threads, one gate per thread.
// w_hh row held as 64 register-resident packed f32 pairs; matvec via FFMA2.
// ---------------------------------------------------------------------------
__global__ __launch_bounds__(384, 1) void gru_scan(
    const float* __restrict__ xgF, const float* __restrict__ xgR,
    const float* __restrict__ whhF, const float* __restrict__ bhhF,
    const float* __restrict__ whhR, const float* __restrict__ bhhR,
    float* __restrict__ out)
{
    int bb  = blockIdx.x >> 1;
    int dir = blockIdx.x & 1;
    const float* xg  = dir ? xgR  : xgF;
    const float* whh = dir ? whhR : whhF;
    const float* bhh = dir ? bhhR : bhhF;

    int g = threadIdx.x;

    // Register-resident packed weight row: 64 pairs
    u64 w2[64];
    {
        const double2* wrow = (const double2*)(whh + (size_t)g * HH);
#pragma unroll
        for (int i = 0; i < 32; i++) {
            double2 v = wrow[i];
            w2[2*i+0] = d2u(v.x);
            w2[2*i+1] = d2u(v.y);
        }
    }
    float bh = bhh[g];

    __shared__ __align__(16) float hs[HH];
    __shared__ float gh[GG];
    if (g < HH) hs[g] = 0.0f;

    const size_t baseXG  = (size_t)bb * TT * GG;
    const size_t baseOut = (size_t)bb * TT * (2*HH) + (size_t)dir * HH;

    // Prefetch first step
    float xr = 0.f, xz = 0.f, xn = 0.f;
    {
        int tt0 = dir ? (TT - 1) : 0;
        if (g < HH) {
            const float* p = xg + baseXG + (size_t)tt0 * GG;
            xr = p[g]; xz = p[g + HH]; xn = p[g + 2*HH];
        }
    }
    __syncthreads();

    const double2* hsd = (const double2*)hs;

    for (int t = 0; t < TT; t++) {
        int tt = dir ? (TT - 1 - t) : t;

        // Prefetch next step's xg (latency hidden behind matvec)
        float nxr = 0.f, nxz = 0.f, nxn = 0.f;
        if (g < HH && t + 1 < TT) {
            int tn = dir ? (tt - 1) : (tt + 1);
            const float* p = xg + baseXG + (size_t)tn * GG;
            nxr = p[g]; nxz = p[g + HH]; nxn = p[g + 2*HH];
        }

        // gh[g] = dot(h, w_hh[g,:]) + b_hh[g]  -- 64 FFMA2
        u64 a0 = 0ull, a1 = 0ull, a2 = 0ull, a3 = 0ull;
#pragma unroll
        for (int i = 0; i < 16; i++) {
            double2 h0 = hsd[2*i];
            double2 h1 = hsd[2*i+1];
            a0 = ffma2(w2[4*i+0], d2u(h0.x), a0);
            a1 = ffma2(w2[4*i+1], d2u(h0.y), a1);
            a2 = ffma2(w2[4*i+2], d2u(h1.x), a2);
            a3 = ffma2(w2[4*i+3], d2u(h1.y), a3);
        }
        float2 p0 = unpack2(a0), p1 = unpack2(a1), p2 = unpack2(a2), p3 = unpack2(a3);
        gh[g] = ((p0.x + p0.y) + (p1.x + p1.y)) + ((p2.x + p2.y) + (p3.x + p3.y)) + bh;
        __syncthreads();

        if (g < HH) {
            float r  = sigf(xr + gh[g]);
            float z  = sigf(xz + gh[g + HH]);
            float n  = tanh_fast(xn + r * gh[g + 2*HH]);
            float hp = hs[g];
            float hn = fmaf(z, hp - n, n);   // (1-z)*n + z*h
            hs[g] = hn;
            out[baseOut + (size_t)tt * (2*HH) + g] = hn;
        }
        __syncthreads();

        xr = nxr; xz = nxz; xn = nxn;
    }
}

// ---------------------------------------------------------------------------
// Final FC
// ---------------------------------------------------------------------------
__global__ __launch_bounds__(256) void fc_kernel(
    const float* __restrict__ h,
    const float* __restrict__ fw,   // [2][256]
    const float* __restrict__ fb,   // [2]
    float* __restrict__ out)        // [rows][2]
{
    int row  = blockIdx.x * 8 + (threadIdx.x >> 5);
    int lane = threadIdx.x & 31;
    const float* hp = h + (size_t)row * (2*HH);
    float a0 = 0.f, a1 = 0.f;
#pragma unroll
    for (int i = 0; i < 8; i++) {
        int k = lane + 32 * i;
        float v = hp[k];
        a0 = fmaf(v, fw[k],       a0);
        a1 = fmaf(v, fw[256 + k], a1);
    }
#pragma unroll
    for (int off = 16; off; off >>= 1) {
        a0 += __shfl_xor_sync(0xffffffffu, a0, off);
        a1 += __shfl_xor_sync(0xffffffffu, a1, off);
    }
    if (lane == 0) {
        out[(size_t)row * 2 + 0] = a0 + fb[0];
        out[(size_t)row * 2 + 1] = a1 + fb[1];
    }
}

// ---------------------------------------------------------------------------
// Launch
// ---------------------------------------------------------------------------
extern "C" void kernel_launch(void* const* d_in, const int* in_sizes, int n_in,
                              void* d_out, int out_size)
{
    const float* x        = (const float*)d_in[0];
    const float* w_ih_l0  = (const float*)d_in[1];
    const float* w_hh_l0  = (const float*)d_in[2];
    const float* b_ih_l0  = (const float*)d_in[3];
    const float* b_hh_l0  = (const float*)d_in[4];
    const float* w_ih_l0r = (const float*)d_in[5];
    const float* w_hh_l0r = (const float*)d_in[6];
    const float* b_ih_l0r = (const float*)d_in[7];
    const float* b_hh_l0r = (const float*)d_in[8];
    const float* w_ih_l1  = (const float*)d_in[9];
    const float* w_hh_l1  = (const float*)d_in[10];
    const float* b_ih_l1  = (const float*)d_in[11];
    const float* b_hh_l1  = (const float*)d_in[12];
    const float* w_ih_l1r = (const float*)d_in[13];
    const float* w_hh_l1r = (const float*)d_in[14];
    const float* b_ih_l1r = (const float*)d_in[15];
    const float* b_hh_l1r = (const float*)d_in[16];
    const float* fc_w     = (const float*)d_in[17];
    const float* fc_b     = (const float*)d_in[18];
    float* out = (float*)d_out;

    float *xgF, *xgR, *hbuf;
    cudaGetSymbolAddress((void**)&xgF,  g_xgF);
    cudaGetSymbolAddress((void**)&xgR,  g_xgR);
    cudaGetSymbolAddress((void**)&hbuf, g_h);

    // Layer 0 input projections (K = 18)
    dim3 gGrid(BTR / 64, GG / 64);
    gemm_tn_bias<<<gGrid, 256>>>(x, DIN, w_ih_l0,  b_ih_l0,  xgF, GG, BTR, GG, DIN);
    gemm_tn_bias<<<gGrid, 256>>>(x, DIN, w_ih_l0r, b_ih_l0r, xgR, GG, BTR, GG, DIN);

    // Layer 0 scan
    gru_scan<<<BB * 2, GG>>>(xgF, xgR, w_hh_l0, b_hh_l0, w_hh_l0r, b_hh_l0r, hbuf);

    // Layer 1 input projections (K = 256)
    dim3 g2Grid(BTR / 128, GG / 128);
    gemm128<<<g2Grid, 256>>>(hbuf, w_ih_l1,  b_ih_l1,  xgF);
    gemm128<<<g2Grid, 256>>>(hbuf, w_ih_l1r, b_ih_l1r, xgR);

    // Layer 1 scan
    gru_scan<<<BB * 2, GG>>>(xgF, xgR, w_hh_l1, b_hh_l1, w_hh_l1r, b_hh_l1r, hbuf);

    // Final FC
    fc_kernel<<<BTR / 8, 256>>>(hbuf, fc_w, fc_b, out);
}

// round 5
// speedup vs baseline: 1.4923x; 1.0726x over previous
#include <cuda_runtime.h>
#include <cuda_bf16.h>
#include <cstddef>

// Problem constants
#define BB   64
#define TT   2048
#define HH   128
#define GG   384     // 3*H
#define DIN  18
#define DOUT 2
#define BTR  (BB*TT)           // 131072 rows
#define GK   256               // layer-1 input width

typedef unsigned long long u64;

// ---------------------------------------------------------------------------
// Scratch (device globals; no allocation allowed)
// ---------------------------------------------------------------------------
static __device__ float g_xgF[(size_t)BTR * GG];   // 201 MB
static __device__ float g_xgR[(size_t)BTR * GG];   // 201 MB
static __device__ float g_h  [(size_t)BTR * 2*HH]; // 134 MB (h0, then reused for h1)

// ---------------------------------------------------------------------------
// Helpers
// ---------------------------------------------------------------------------
__device__ __forceinline__ u64 ffma2(u64 a, u64 b, u64 c) {
    u64 d;
    asm("fma.rn.f32x2 %0, %1, %2, %3;" : "=l"(d) : "l"(a), "l"(b), "l"(c));
    return d;
}
__device__ __forceinline__ u64 d2u(double x) {
    return (u64)__double_as_longlong(x);
}
__device__ __forceinline__ u64 pack2(float a) {     // (a, a) pair
    u64 d;
    asm("mov.b64 %0, {%1, %1};" : "=l"(d) : "f"(a));
    return d;
}
__device__ __forceinline__ float2 unpack2(u64 v) {
    float2 r;
    asm("mov.b64 {%0, %1}, %2;" : "=f"(r.x), "=f"(r.y) : "l"(v));
    return r;
}
__device__ __forceinline__ float sigf(float x) {
    return 1.0f / (1.0f + __expf(-x));
}
__device__ __forceinline__ float tanh_fast(float x) {
    float xc = fminf(fmaxf(x, -20.0f), 20.0f);
    float e  = __expf(-2.0f * xc);
    return (1.0f - e) / (1.0f + e);
}

// ---------------------------------------------------------------------------
// Generic fp32 GEMM (K=18 projections): C[M][N] = A[M][K]*B[N][K]^T + bias[N]
// ---------------------------------------------------------------------------
__global__ __launch_bounds__(256) void gemm_tn_bias(
    const float* __restrict__ A, int lda,
    const float* __restrict__ Bw,
    const float* __restrict__ bias,
    float* __restrict__ C, int ldc,
    int M, int N, int K)
{
    const int BM = 64, BN = 64, BK = 16;
    const int PAD = 8;
    __shared__ __align__(16) float As[BK][BM + PAD];
    __shared__ __align__(16) float Bs[BK][BN + PAD];

    int tid = threadIdx.x;
    int tx = tid & 15;
    int ty = tid >> 4;
    int m0 = blockIdx.x * BM;
    int n0 = blockIdx.y * BN;

    float acc[4][4];
#pragma unroll
    for (int i = 0; i < 4; i++)
#pragma unroll
        for (int j = 0; j < 4; j++) acc[i][j] = 0.0f;

    int nkt = (K + BK - 1) / BK;
    for (int kt = 0; kt < nkt; kt++) {
        int k0 = kt * BK;
#pragma unroll
        for (int r = 0; r < 4; r++) {
            int idx = tid + r * 256;
            int m = idx >> 4;
            int k = idx & 15;
            float va = 0.0f, vb = 0.0f;
            if (k0 + k < K) {
                va = A[(size_t)(m0 + m) * lda + k0 + k];
                vb = Bw[(size_t)(n0 + m) * K + k0 + k];
            }
            As[k][m] = va;
            Bs[k][m] = vb;
        }
        __syncthreads();
#pragma unroll
        for (int k = 0; k < BK; k++) {
            float4 a = *(const float4*)&As[k][ty * 4];
            float4 b = *(const float4*)&Bs[k][tx * 4];
            float av[4] = {a.x, a.y, a.z, a.w};
            float bv[4] = {b.x, b.y, b.z, b.w};
#pragma unroll
            for (int i = 0; i < 4; i++)
#pragma unroll
                for (int j = 0; j < 4; j++)
                    acc[i][j] = fmaf(av[i], bv[j], acc[i][j]);
        }
        __syncthreads();
    }

    float4 bv = *(const float4*)&bias[n0 + tx * 4];
#pragma unroll
    for (int i = 0; i < 4; i++) {
        int m = m0 + ty * 4 + i;
        float4 o = make_float4(acc[i][0] + bv.x, acc[i][1] + bv.y,
                               acc[i][2] + bv.z, acc[i][3] + bv.w);
        *(float4*)&C[(size_t)m * ldc + n0 + tx * 4] = o;
    }
}

// ---------------------------------------------------------------------------
// K=256 GEMM with FFMA2 (at SIMT issue floor):
// C[BTR][384] = A[BTR][256]*Bw[384][256]^T + bias
// ---------------------------------------------------------------------------
__global__ __launch_bounds__(256, 2) void gemm128(
    const float* __restrict__ A,      // [BTR][256]
    const float* __restrict__ Bw,     // [384][256]
    const float* __restrict__ bias,   // [384]
    float* __restrict__ C)            // [BTR][384]
{
    __shared__ __align__(16) float As[16][132];
    __shared__ __align__(16) float Bs[16][132];

    int tid = threadIdx.x;
    int tx = tid & 15;           // n group
    int ty = tid >> 4;           // m group
    int m0 = blockIdx.x * 128;
    int n0 = blockIdx.y * 128;

    u64 acc[8][4];
#pragma unroll
    for (int i = 0; i < 8; i++)
#pragma unroll
        for (int j = 0; j < 4; j++) acc[i][j] = 0ull;

    float bias_r[8];
#pragma unroll
    for (int j = 0; j < 8; j++) bias_r[j] = bias[n0 + tx * 8 + j];

    int rowA = tid >> 2;          // 0..63
    int kq   = (tid & 3) * 4;     // 0,4,8,12

    for (int k0 = 0; k0 < GK; k0 += 16) {
#pragma unroll
        for (int p = 0; p < 2; p++) {
            int r = rowA + p * 64;
            float4 a = *(const float4*)&A [(size_t)(m0 + r) * GK + k0 + kq];
            float4 b = *(const float4*)&Bw[(size_t)(n0 + r) * GK + k0 + kq];
            As[kq + 0][r] = a.x;
            As[kq + 1][r] = a.y;
            As[kq + 2][r] = a.z;
            As[kq + 3][r] = a.w;
            Bs[kq + 0][r] = b.x;
            Bs[kq + 1][r] = b.y;
            Bs[kq + 2][r] = b.z;
            Bs[kq + 3][r] = b.w;
        }
        __syncthreads();
#pragma unroll
        for (int k = 0; k < 16; k++) {
            float4 av0 = *(const float4*)&As[k][ty * 8];
            float4 av1 = *(const float4*)&As[k][ty * 8 + 4];
            double2 bp0 = *(const double2*)&Bs[k][tx * 8];
            double2 bp1 = *(const double2*)&Bs[k][tx * 8 + 4];
            u64 bb[4] = {d2u(bp0.x), d2u(bp0.y), d2u(bp1.x), d2u(bp1.y)};
            u64 aa[8] = {pack2(av0.x), pack2(av0.y), pack2(av0.z), pack2(av0.w),
                         pack2(av1.x), pack2(av1.y), pack2(av1.z), pack2(av1.w)};
#pragma unroll
            for (int i = 0; i < 8; i++)
#pragma unroll
                for (int j = 0; j < 4; j++)
                    acc[i][j] = ffma2(aa[i], bb[j], acc[i][j]);
        }
        __syncthreads();
    }

#pragma unroll
    for (int i = 0; i < 8; i++) {
        int m = m0 + ty * 8 + i;
        float2 p0 = unpack2(acc[i][0]);
        float2 p1 = unpack2(acc[i][1]);
        float2 p2 = unpack2(acc[i][2]);
        float2 p3 = unpack2(acc[i][3]);
        float4 o0 = make_float4(p0.x + bias_r[0], p0.y + bias_r[1],
                                p1.x + bias_r[2], p1.y + bias_r[3]);
        float4 o1 = make_float4(p2.x + bias_r[4], p2.y + bias_r[5],
                                p3.x + bias_r[6], p3.y + bias_r[7]);
        float* crow = &C[(size_t)m * GG + n0 + tx * 8];
        *(float4*)(crow)     = o0;
        *(float4*)(crow + 4) = o1;
    }
}

// ---------------------------------------------------------------------------
// GRU scan, role-structured step:
// grid = 128 (one block per (batch,dir)), 384 threads, thread g = gate row g.
// Roles: g<128 -> r gate, g<256 -> z gate, g>=256 -> n gate + h update.
//  * per-step xg prefetch: ONE branchless coalesced LDG per thread (xg[t*384+g])
//  * r/z threads apply sigmoid themselves right after their matvec acc
//    (spreads MUFU over 8 warps, removes gh smem trip for r,z)
//  * n threads keep gh_n + xn in registers; phase B does tanh + h update
// ---------------------------------------------------------------------------
__global__ __launch_bounds__(384, 1) void gru_scan(
    const float* __restrict__ xgF, const float* __restrict__ xgR,
    const float* __restrict__ whhF, const float* __restrict__ bhhF,
    const float* __restrict__ whhR, const float* __restrict__ bhhR,
    float* __restrict__ out)
{
    int bb  = blockIdx.x >> 1;
    int dir = blockIdx.x & 1;
    const float* xg  = dir ? xgR  : xgF;
    const float* whh = dir ? whhR : whhF;
    const float* bhh = dir ? bhhR : bhhF;

    int g = threadIdx.x;
    int j = g & 127;

    // Register-resident packed weight row: 64 pairs
    u64 w2[64];
    {
        const double2* wrow = (const double2*)(whh + (size_t)g * HH);
#pragma unroll
        for (int i = 0; i < 32; i++) {
            double2 v = wrow[i];
            w2[2*i+0] = d2u(v.x);
            w2[2*i+1] = d2u(v.y);
        }
    }
    float bh = bhh[g];

    __shared__ __align__(16) float hs[HH];
    __shared__ float rz[2 * HH];           // r in [0,128), z in [128,256)
    if (g < HH) hs[g] = 0.0f;

    // Per-step xg pointer walk: thread g reads xg[base + t*GG + g]
    const float* xp   = xg + (size_t)bb * TT * GG + (size_t)(dir ? (TT - 1) : 0) * GG + g;
    const ptrdiff_t xstep = dir ? -(ptrdiff_t)GG : (ptrdiff_t)GG;

    float*       op    = out + (size_t)bb * TT * (2*HH)
                             + (size_t)(dir ? (TT - 1) : 0) * (2*HH)
                             + (size_t)dir * HH + j;
    const ptrdiff_t ostep = dir ? -(ptrdiff_t)(2*HH) : (ptrdiff_t)(2*HH);

    // Preload first xg value (branchless)
    float xv = __ldg(xp);
    xp += xstep;
    __syncthreads();

    const double2* hsd = (const double2*)hs;

    for (int t = 0; t < TT; t++) {
        // Branchless prefetch of next step's value (last iter re-reads: harmless)
        const float* xpn = (t + 1 < TT) ? xp : (xp - xstep);
        float xv_next = __ldg(xpn);

        // Matvec: acc = dot(h, w_hh[g,:])  -- 64 FFMA2, 4 chains
        u64 a0 = 0ull, a1 = 0ull, a2 = 0ull, a3 = 0ull;
#pragma unroll
        for (int i = 0; i < 16; i++) {
            double2 h0 = hsd[2*i];
            double2 h1 = hsd[2*i+1];
            a0 = ffma2(w2[4*i+0], d2u(h0.x), a0);
            a1 = ffma2(w2[4*i+1], d2u(h0.y), a1);
            a2 = ffma2(w2[4*i+2], d2u(h1.x), a2);
            a3 = ffma2(w2[4*i+3], d2u(h1.y), a3);
        }
        float2 p0 = unpack2(a0), p1 = unpack2(a1), p2 = unpack2(a2), p3 = unpack2(a3);
        float acc = ((p0.x + p0.y) + (p1.x + p1.y)) + ((p2.x + p2.y) + (p3.x + p3.y)) + bh;

        float gn = acc + xv;      // for r/z roles: pre-activation; for n role: partial
        if (g < 2 * HH) {
            rz[g] = sigf(gn);     // r or z, finished here (8 warps share the MUFU work)
        } else {
            gn = acc;             // n role: keep gh_n (xn enters inside tanh with r*)
        }
        __syncthreads();

        if (g >= 2 * HH) {
            float r  = rz[j];
            float z  = rz[j + HH];
            float n  = tanh_fast(fmaf(r, gn, xv));   // xv = xn here
            float hp = hs[j];
            float hn = fmaf(z, hp - n, n);           // (1-z)*n + z*h
            hs[j] = hn;
            *op = hn;
        }
        __syncthreads();

        xv = xv_next;
        xp += xstep;
        op += ostep;
    }
}

// ---------------------------------------------------------------------------
// Final FC
// ---------------------------------------------------------------------------
__global__ __launch_bounds__(256) void fc_kernel(
    const float* __restrict__ h,
    const float* __restrict__ fw,   // [2][256]
    const float* __restrict__ fb,   // [2]
    float* __restrict__ out)        // [rows][2]
{
    int row  = blockIdx.x * 8 + (threadIdx.x >> 5);
    int lane = threadIdx.x & 31;
    const float* hp = h + (size_t)row * (2*HH);
    float a0 = 0.f, a1 = 0.f;
#pragma unroll
    for (int i = 0; i < 8; i++) {
        int k = lane + 32 * i;
        float v = hp[k];
        a0 = fmaf(v, fw[k],       a0);
        a1 = fmaf(v, fw[256 + k], a1);
    }
#pragma unroll
    for (int off = 16; off; off >>= 1) {
        a0 += __shfl_xor_sync(0xffffffffu, a0, off);
        a1 += __shfl_xor_sync(0xffffffffu, a1, off);
    }
    if (lane == 0) {
        out[(size_t)row * 2 + 0] = a0 + fb[0];
        out[(size_t)row * 2 + 1] = a1 + fb[1];
    }
}

// ---------------------------------------------------------------------------
// Launch
// ---------------------------------------------------------------------------
extern "C" void kernel_launch(void* const* d_in, const int* in_sizes, int n_in,
                              void* d_out, int out_size)
{
    const float* x        = (const float*)d_in[0];
    const float* w_ih_l0  = (const float*)d_in[1];
    const float* w_hh_l0  = (const float*)d_in[2];
    const float* b_ih_l0  = (const float*)d_in[3];
    const float* b_hh_l0  = (const float*)d_in[4];
    const float* w_ih_l0r = (const float*)d_in[5];
    const float* w_hh_l0r = (const float*)d_in[6];
    const float* b_ih_l0r = (const float*)d_in[7];
    const float* b_hh_l0r = (const float*)d_in[8];
    const float* w_ih_l1  = (const float*)d_in[9];
    const float* w_hh_l1  = (const float*)d_in[10];
    const float* b_ih_l1  = (const float*)d_in[11];
    const float* b_hh_l1  = (const float*)d_in[12];
    const float* w_ih_l1r = (const float*)d_in[13];
    const float* w_hh_l1r = (const float*)d_in[14];
    const float* b_ih_l1r = (const float*)d_in[15];
    const float* b_hh_l1r = (const float*)d_in[16];
    const float* fc_w     = (const float*)d_in[17];
    const float* fc_b     = (const float*)d_in[18];
    float* out = (float*)d_out;

    float *xgF, *xgR, *hbuf;
    cudaGetSymbolAddress((void**)&xgF,  g_xgF);
    cudaGetSymbolAddress((void**)&xgR,  g_xgR);
    cudaGetSymbolAddress((void**)&hbuf, g_h);

    // Layer 0 input projections (K = 18)
    dim3 gGrid(BTR / 64, GG / 64);
    gemm_tn_bias<<<gGrid, 256>>>(x, DIN, w_ih_l0,  b_ih_l0,  xgF, GG, BTR, GG, DIN);
    gemm_tn_bias<<<gGrid, 256>>>(x, DIN, w_ih_l0r, b_ih_l0r, xgR, GG, BTR, GG, DIN);

    // Layer 0 scan
    gru_scan<<<BB * 2, GG>>>(xgF, xgR, w_hh_l0, b_hh_l0, w_hh_l0r, b_hh_l0r, hbuf);

    // Layer 1 input projections (K = 256)
    dim3 g2Grid(BTR / 128, GG / 128);
    gemm128<<<g2Grid, 256>>>(hbuf, w_ih_l1,  b_ih_l1,  xgF);
    gemm128<<<g2Grid, 256>>>(hbuf, w_ih_l1r, b_ih_l1r, xgR);

    // Layer 1 scan
    gru_scan<<<BB * 2, GG>>>(xgF, xgR, w_hh_l1, b_hh_l1, w_hh_l1r, b_hh_l1r, hbuf);

    // Final FC
    fc_kernel<<<BTR / 8, 256>>>(hbuf, fc_w, fc_b, out);
}

// round 8
// speedup vs baseline: 1.5814x; 1.0597x over previous
#include <cuda_runtime.h>
#include <cuda_bf16.h>
#include <cstddef>
#include <cstdint>

// Problem constants
#define BB   64
#define TT   2048
#define HH   128
#define GG   384     // 3*H
#define DIN  18
#define DOUT 2
#define BTR  (BB*TT)           // 131072 rows
#define GK   256               // layer-1 input width

typedef unsigned long long u64;

// ---------------------------------------------------------------------------
// Scratch (device globals; no allocation allowed)
// ---------------------------------------------------------------------------
static __device__ float          g_xgF[(size_t)BTR * GG];   // 201 MB
static __device__ float          g_xgR[(size_t)BTR * GG];   // 201 MB
static __device__ unsigned short g_hHi[(size_t)BTR * 256];  // 67 MB (bf16 hi plane)
static __device__ unsigned short g_hLo[(size_t)BTR * 256];  // 67 MB (bf16 lo plane)

// ---------------------------------------------------------------------------
// Helpers
// ---------------------------------------------------------------------------
__device__ __forceinline__ u64 ffma2(u64 a, u64 b, u64 c) {
    u64 d;
    asm("fma.rn.f32x2 %0, %1, %2, %3;" : "=l"(d) : "l"(a), "l"(b), "l"(c));
    return d;
}
__device__ __forceinline__ u64 d2u(double x) {
    return (u64)__double_as_longlong(x);
}
__device__ __forceinline__ float2 unpack2(u64 v) {
    float2 r;
    asm("mov.b64 {%0, %1}, %2;" : "=f"(r.x), "=f"(r.y) : "l"(v));
    return r;
}
__device__ __forceinline__ float sigf(float x) {
    return 1.0f / (1.0f + __expf(-x));
}
__device__ __forceinline__ float tanh_fast(float x) {
    float xc = fminf(fmaxf(x, -20.0f), 20.0f);
    float e  = __expf(-2.0f * xc);
    return (1.0f - e) / (1.0f + e);
}
__device__ __forceinline__ uint32_t smem_u32(const void* p) {
    uint32_t a;
    asm("{ .reg .u64 t; cvta.to.shared.u64 t, %1; cvt.u32.u64 %0, t; }" : "=r"(a) : "l"(p));
    return a;
}

// ---------------------------------------------------------------------------
// Generic fp32 GEMM (K=18 projections): C[M][N] = A[M][K]*B[N][K]^T + bias[N]
// ---------------------------------------------------------------------------
__global__ __launch_bounds__(256) void gemm_tn_bias(
    const float* __restrict__ A, int lda,
    const float* __restrict__ Bw,
    const float* __restrict__ bias,
    float* __restrict__ C, int ldc,
    int M, int N, int K)
{
    const int BM = 64, BN = 64, BK = 16;
    const int PAD = 8;
    __shared__ __align__(16) float As[BK][BM + PAD];
    __shared__ __align__(16) float Bs[BK][BN + PAD];

    int tid = threadIdx.x;
    int tx = tid & 15;
    int ty = tid >> 4;
    int m0 = blockIdx.x * BM;
    int n0 = blockIdx.y * BN;

    float acc[4][4];
#pragma unroll
    for (int i = 0; i < 4; i++)
#pragma unroll
        for (int j = 0; j < 4; j++) acc[i][j] = 0.0f;

    int nkt = (K + BK - 1) / BK;
    for (int kt = 0; kt < nkt; kt++) {
        int k0 = kt * BK;
#pragma unroll
        for (int r = 0; r < 4; r++) {
            int idx = tid + r * 256;
            int m = idx >> 4;
            int k = idx & 15;
            float va = 0.0f, vb = 0.0f;
            if (k0 + k < K) {
                va = A[(size_t)(m0 + m) * lda + k0 + k];
                vb = Bw[(size_t)(n0 + m) * K + k0 + k];
            }
            As[k][m] = va;
            Bs[k][m] = vb;
        }
        __syncthreads();
#pragma unroll
        for (int k = 0; k < BK; k++) {
            float4 a = *(const float4*)&As[k][ty * 4];
            float4 b = *(const float4*)&Bs[k][tx * 4];
            float av[4] = {a.x, a.y, a.z, a.w};
            float bv[4] = {b.x, b.y, b.z, b.w};
#pragma unroll
            for (int i = 0; i < 4; i++)
#pragma unroll
                for (int j = 0; j < 4; j++)
                    acc[i][j] = fmaf(av[i], bv[j], acc[i][j]);
        }
        __syncthreads();
    }

    float4 bv = *(const float4*)&bias[n0 + tx * 4];
#pragma unroll
    for (int i = 0; i < 4; i++) {
        int m = m0 + ty * 4 + i;
        float4 o = make_float4(acc[i][0] + bv.x, acc[i][1] + bv.y,
                               acc[i][2] + bv.z, acc[i][3] + bv.w);
        *(float4*)&C[(size_t)m * ldc + n0 + tx * 4] = o;
    }
}

// ---------------------------------------------------------------------------
// Tensor-core GEMM via mma.sync (K=256): C[BTR][384] = A * W^T + bias
// A given as bf16 hi/lo planes [BTR][256]; W fp32 [384][256] split on the fly.
// 128x128 tile/CTA, 8 warps each 64x32, K chunked x64, 3-term bf16 MMA.
// smem: 4 planes of [128][72] bf16 (pad row to 144B -> conflict-free LDSM).
// ---------------------------------------------------------------------------
#define SA 72
#define SM_PLANE (128 * SA * 2)     // 18432 bytes per plane
__global__ __launch_bounds__(256, 2) void hmma_gemm(
    const unsigned short* __restrict__ Ahi,
    const unsigned short* __restrict__ Alo,
    const float* __restrict__ W,      // [384][256]
    const float* __restrict__ bias,   // [384]
    float* __restrict__ C)            // [BTR][384]
{
    extern __shared__ __align__(16) unsigned short smh[];
    unsigned short* sAhi = smh;
    unsigned short* sAlo = sAhi + 128 * SA;
    unsigned short* sWhi = sAlo + 128 * SA;
    unsigned short* sWlo = sWhi + 128 * SA;

    int tid  = threadIdx.x;
    int lane = tid & 31;
    int warp = tid >> 5;
    size_t m0 = (size_t)blockIdx.x * 128;
    int    n0 = blockIdx.y * 128;
    int m_off = (warp & 1) * 64;
    int n_off = (warp >> 1) * 32;

    float acc[4][4][4];     // [mt][nt][frag]
#pragma unroll
    for (int a = 0; a < 4; a++)
#pragma unroll
        for (int b = 0; b < 4; b++)
#pragma unroll
            for (int c = 0; c < 4; c++) acc[a][b][c] = 0.0f;

    // Loader indices
    int r  = tid >> 1;            // 0..127
    int c0 = (tid & 1) * 32;      // 0 or 32
    const size_t arow = (m0 + r) * GK;
    const size_t wrow = (size_t)(n0 + r) * GK;

    // ldmatrix per-lane address components (element units)
    uint32_t sb = smem_u32(smh);
    int ln  = lane & 7;
    int sel = lane >> 3;
    int aoff = (m_off + ln + (sel & 1) * 8) * SA + (sel >> 1) * 8;
    int half = (lane >> 3) & 1;         // lanes 16-31: addresses unused by x2
    int boff = (n_off + (lane & 7)) * SA + half * 8;

    for (int ch = 0; ch < 4; ch++) {
        int kb = ch * 64 + c0;
        __syncthreads();   // previous chunk's LDSM complete before overwrite

        // A planes: 32 bf16 each (4 x uint4)
#pragma unroll
        for (int i = 0; i < 4; i++) {
            uint4 va = *(const uint4*)&Ahi[arow + kb + 8 * i];
            *(uint4*)&sAhi[r * SA + c0 + 8 * i] = va;
        }
#pragma unroll
        for (int i = 0; i < 4; i++) {
            uint4 vl = *(const uint4*)&Alo[arow + kb + 8 * i];
            *(uint4*)&sAlo[r * SA + c0 + 8 * i] = vl;
        }
        // W: 32 fp32 -> bf16 hi/lo split
#pragma unroll
        for (int i = 0; i < 8; i++) {
            float4 wv = *(const float4*)&W[wrow + kb + 4 * i];
            __nv_bfloat16 h0 = __float2bfloat16(wv.x);
            __nv_bfloat16 h1 = __float2bfloat16(wv.y);
            __nv_bfloat16 h2 = __float2bfloat16(wv.z);
            __nv_bfloat16 h3 = __float2bfloat16(wv.w);
            __nv_bfloat16 l0 = __float2bfloat16(wv.x - __bfloat162float(h0));
            __nv_bfloat16 l1 = __float2bfloat16(wv.y - __bfloat162float(h1));
            __nv_bfloat16 l2 = __float2bfloat16(wv.z - __bfloat162float(h2));
            __nv_bfloat16 l3 = __float2bfloat16(wv.w - __bfloat162float(h3));
            uint2 uh, ul;
            uh.x = (uint32_t)__bfloat16_as_ushort(h0) | ((uint32_t)__bfloat16_as_ushort(h1) << 16);
            uh.y = (uint32_t)__bfloat16_as_ushort(h2) | ((uint32_t)__bfloat16_as_ushort(h3) << 16);
            ul.x = (uint32_t)__bfloat16_as_ushort(l0) | ((uint32_t)__bfloat16_as_ushort(l1) << 16);
            ul.y = (uint32_t)__bfloat16_as_ushort(l2) | ((uint32_t)__bfloat16_as_ushort(l3) << 16);
            *(uint2*)&sWhi[r * SA + c0 + 4 * i] = uh;
            *(uint2*)&sWlo[r * SA + c0 + 4 * i] = ul;
        }
        __syncthreads();

        // 3 terms: (Ahi,Whi), (Ahi,Wlo), (Alo,Whi)
#pragma unroll
        for (int term = 0; term < 3; term++) {
            uint32_t aBase = sb + (term == 2 ? SM_PLANE : 0) + (uint32_t)aoff * 2;
            uint32_t bBase = sb + (term == 1 ? 3 * SM_PLANE : 2 * SM_PLANE)
                           + (uint32_t)boff * 2;
#pragma unroll
            for (int kk = 0; kk < 4; kk++) {
                uint32_t af[4][4];
#pragma unroll
                for (int mt = 0; mt < 4; mt++) {
                    uint32_t addr = aBase + (uint32_t)(mt * 16 * SA + kk * 16) * 2;
                    asm volatile(
                        "ldmatrix.sync.aligned.m8n8.x4.shared.b16 {%0,%1,%2,%3}, [%4];"
                        : "=r"(af[mt][0]), "=r"(af[mt][1]), "=r"(af[mt][2]), "=r"(af[mt][3])
                        : "r"(addr));
                }
                uint32_t bf[4][2];
#pragma unroll
                for (int nt = 0; nt < 4; nt++) {
                    uint32_t addr = bBase + (uint32_t)(nt * 8 * SA + kk * 16) * 2;
                    asm volatile(
                        "ldmatrix.sync.aligned.m8n8.x2.shared.b16 {%0,%1}, [%2];"
                        : "=r"(bf[nt][0]), "=r"(bf[nt][1])
                        : "r"(addr));
                }
#pragma unroll
                for (int mt = 0; mt < 4; mt++)
#pragma unroll
                    for (int nt = 0; nt < 4; nt++) {
                        asm volatile(
                            "mma.sync.aligned.m16n8k16.row.col.f32.bf16.bf16.f32 "
                            "{%0,%1,%2,%3}, {%4,%5,%6,%7}, {%8,%9}, {%0,%1,%2,%3};"
                            : "+f"(acc[mt][nt][0]), "+f"(acc[mt][nt][1]),
                              "+f"(acc[mt][nt][2]), "+f"(acc[mt][nt][3])
                            : "r"(af[mt][0]), "r"(af[mt][1]), "r"(af[mt][2]), "r"(af[mt][3]),
                              "r"(bf[nt][0]), "r"(bf[nt][1]));
                    }
            }
        }
    }

    // Epilogue: C frag mapping: c0,c1 -> (row=lane/4, col=2*(lane%4)+{0,1}); c2,c3 -> row+8
    int cr  = lane >> 2;
    int cc2 = (lane & 3) * 2;
#pragma unroll
    for (int nt = 0; nt < 4; nt++) {
        int n = n0 + n_off + nt * 8 + cc2;
        float2 bq = *(const float2*)&bias[n];
#pragma unroll
        for (int mt = 0; mt < 4; mt++) {
            size_t m = m0 + m_off + mt * 16 + cr;
            float2 o0 = make_float2(acc[mt][nt][0] + bq.x, acc[mt][nt][1] + bq.y);
            float2 o1 = make_float2(acc[mt][nt][2] + bq.x, acc[mt][nt][3] + bq.y);
            *(float2*)&C[m * GG + n]       = o0;
            *(float2*)&C[(m + 8) * GG + n] = o1;
        }
    }
}

// ---------------------------------------------------------------------------
// GRU scan (R5 role-structured). Output: bf16 hi/lo planes [BTR][256].
// ---------------------------------------------------------------------------
__global__ __launch_bounds__(384, 1) void gru_scan(
    const float* __restrict__ xgF, const float* __restrict__ xgR,
    const float* __restrict__ whhF, const float* __restrict__ bhhF,
    const float* __restrict__ whhR, const float* __restrict__ bhhR,
    unsigned short* __restrict__ outHi, unsigned short* __restrict__ outLo)
{
    int bb  = blockIdx.x >> 1;
    int dir = blockIdx.x & 1;
    const float* xg  = dir ? xgR  : xgF;
    const float* whh = dir ? whhR : whhF;
    const float* bhh = dir ? bhhR : bhhF;

    int g = threadIdx.x;
    int j = g & 127;

    u64 w2[64];
    {
        const double2* wrow = (const double2*)(whh + (size_t)g * HH);
#pragma unroll
        for (int i = 0; i < 32; i++) {
            double2 v = wrow[i];
            w2[2*i+0] = d2u(v.x);
            w2[2*i+1] = d2u(v.y);
        }
    }
    float bh = bhh[g];

    __shared__ __align__(16) float hs[HH];
    __shared__ float rz[2 * HH];
    if (g < HH) hs[g] = 0.0f;

    const float* xp = xg + (size_t)bb * TT * GG + (size_t)(dir ? (TT - 1) : 0) * GG + g;
    const ptrdiff_t xstep = dir ? -(ptrdiff_t)GG : (ptrdiff_t)GG;

    size_t oidx = (size_t)bb * TT * 256 + (size_t)(dir ? (TT - 1) : 0) * 256
                + (size_t)dir * HH + j;
    const ptrdiff_t ostep = dir ? -(ptrdiff_t)256 : (ptrdiff_t)256;

    float xv = __ldg(xp);
    xp += xstep;
    __syncthreads();

    const double2* hsd = (const double2*)hs;

    for (int t = 0; t < TT; t++) {
        const float* xpn = (t + 1 < TT) ? xp : (xp - xstep);
        float xv_next = __ldg(xpn);

        u64 a0 = 0ull, a1 = 0ull, a2 = 0ull, a3 = 0ull;
#pragma unroll
        for (int i = 0; i < 16; i++) {
            double2 h0 = hsd[2*i];
            double2 h1 = hsd[2*i+1];
            a0 = ffma2(w2[4*i+0], d2u(h0.x), a0);
            a1 = ffma2(w2[4*i+1], d2u(h0.y), a1);
            a2 = ffma2(w2[4*i+2], d2u(h1.x), a2);
            a3 = ffma2(w2[4*i+3], d2u(h1.y), a3);
        }
        float2 p0 = unpack2(a0), p1 = unpack2(a1), p2 = unpack2(a2), p3 = unpack2(a3);
        float acc = ((p0.x + p0.y) + (p1.x + p1.y)) + ((p2.x + p2.y) + (p3.x + p3.y)) + bh;

        float gn = acc + xv;
        if (g < 2 * HH) {
            rz[g] = sigf(gn);
        } else {
            gn = acc;
        }
        __syncthreads();

        if (g >= 2 * HH) {
            float r  = rz[j];
            float z  = rz[j + HH];
            float n  = tanh_fast(fmaf(r, gn, xv));
            float hp = hs[j];
            float hn = fmaf(z, hp - n, n);
            hs[j] = hn;
            __nv_bfloat16 bhi = __float2bfloat16(hn);
            __nv_bfloat16 blo = __float2bfloat16(hn - __bfloat162float(bhi));
            outHi[oidx] = __bfloat16_as_ushort(bhi);
            outLo[oidx] = __bfloat16_as_ushort(blo);
        }
        __syncthreads();

        xv = xv_next;
        xp += xstep;
        oidx += ostep;
    }
}

// ---------------------------------------------------------------------------
// Final FC: reads h1 = hi + lo planes
// ---------------------------------------------------------------------------
__global__ __launch_bounds__(256) void fc_kernel(
    const unsigned short* __restrict__ hHi,
    const unsigned short* __restrict__ hLo,
    const float* __restrict__ fw,   // [2][256]
    const float* __restrict__ fb,   // [2]
    float* __restrict__ out)        // [rows][2]
{
    int row  = blockIdx.x * 8 + (threadIdx.x >> 5);
    int lane = threadIdx.x & 31;
    size_t base = (size_t)row * 256;
    float a0 = 0.f, a1 = 0.f;
#pragma unroll
    for (int i = 0; i < 8; i++) {
        int k = lane + 32 * i;
        float v = __bfloat162float(__ushort_as_bfloat16(hHi[base + k]))
                + __bfloat162float(__ushort_as_bfloat16(hLo[base + k]));
        a0 = fmaf(v, fw[k],       a0);
        a1 = fmaf(v, fw[256 + k], a1);
    }
#pragma unroll
    for (int off = 16; off; off >>= 1) {
        a0 += __shfl_xor_sync(0xffffffffu, a0, off);
        a1 += __shfl_xor_sync(0xffffffffu, a1, off);
    }
    if (lane == 0) {
        out[(size_t)row * 2 + 0] = a0 + fb[0];
        out[(size_t)row * 2 + 1] = a1 + fb[1];
    }
}

// ---------------------------------------------------------------------------
// Launch
// ---------------------------------------------------------------------------
extern "C" void kernel_launch(void* const* d_in, const int* in_sizes, int n_in,
                              void* d_out, int out_size)
{
    const float* x        = (const float*)d_in[0];
    const float* w_ih_l0  = (const float*)d_in[1];
    const float* w_hh_l0  = (const float*)d_in[2];
    const float* b_ih_l0  = (const float*)d_in[3];
    const float* b_hh_l0  = (const float*)d_in[4];
    const float* w_ih_l0r = (const float*)d_in[5];
    const float* w_hh_l0r = (const float*)d_in[6];
    const float* b_ih_l0r = (const float*)d_in[7];
    const float* b_hh_l0r = (const float*)d_in[8];
    const float* w_ih_l1  = (const float*)d_in[9];
    const float* w_hh_l1  = (const float*)d_in[10];
    const float* b_ih_l1  = (const float*)d_in[11];
    const float* b_hh_l1  = (const float*)d_in[12];
    const float* w_ih_l1r = (const float*)d_in[13];
    const float* w_hh_l1r = (const float*)d_in[14];
    const float* b_ih_l1r = (const float*)d_in[15];
    const float* b_hh_l1r = (const float*)d_in[16];
    const float* fc_w     = (const float*)d_in[17];
    const float* fc_b     = (const float*)d_in[18];
    float* out = (float*)d_out;

    float *xgF, *xgR;
    unsigned short *hHi, *hLo;
    cudaGetSymbolAddress((void**)&xgF, g_xgF);
    cudaGetSymbolAddress((void**)&xgR, g_xgR);
    cudaGetSymbolAddress((void**)&hHi, g_hHi);
    cudaGetSymbolAddress((void**)&hLo, g_hLo);

    static int smem_set = 0;
    const int HM_SMEM = 4 * SM_PLANE;   // 73728 B
    if (!smem_set) {
        cudaFuncSetAttribute(hmma_gemm, cudaFuncAttributeMaxDynamicSharedMemorySize, HM_SMEM);
        smem_set = 1;
    }

    // Layer 0 input projections (K = 18)
    dim3 gGrid(BTR / 64, GG / 64);
    gemm_tn_bias<<<gGrid, 256>>>(x, DIN, w_ih_l0,  b_ih_l0,  xgF, GG, BTR, GG, DIN);
    gemm_tn_bias<<<gGrid, 256>>>(x, DIN, w_ih_l0r, b_ih_l0r, xgR, GG, BTR, GG, DIN);

    // Layer 0 scan -> h0 bf16 hi/lo planes
    gru_scan<<<BB * 2, GG>>>(xgF, xgR, w_hh_l0, b_hh_l0, w_hh_l0r, b_hh_l0r, hHi, hLo);

    // Layer 1 input projections (K = 256): tensor-core GEMM via mma.sync
    dim3 tcGrid(BTR / 128, GG / 128);  // 1024 x 3
    hmma_gemm<<<tcGrid, 256, HM_SMEM>>>(hHi, hLo, w_ih_l1,  b_ih_l1,  xgF);
    hmma_gemm<<<tcGrid, 256, HM_SMEM>>>(hHi, hLo, w_ih_l1r, b_ih_l1r, xgR);

    // Layer 1 scan -> h1 planes (overwrites h0 planes; GEMMs already consumed them)
    gru_scan<<<BB * 2, GG>>>(xgF, xgR, w_hh_l1, b_hh_l1, w_hh_l1r, b_hh_l1r, hHi, hLo);

    // Final FC
    fc_kernel<<<BTR / 8, 256>>>(hHi, hLo, fc_w, fc_b, out);
}

// round 10
// speedup vs baseline: 1.6703x; 1.0562x over previous
#include <cuda_runtime.h>
#include <cuda_bf16.h>
#include <cstddef>
#include <cstdint>

// Problem constants
#define BB   64
#define TT   2048
#define HH   128
#define GG   384     // 3*H
#define DIN  18
#define DOUT 2
#define BTR  (BB*TT)           // 131072 rows
#define GK   256               // layer-1 input width

typedef unsigned long long u64;

// ---------------------------------------------------------------------------
// Scratch (device globals; no allocation allowed)
// ---------------------------------------------------------------------------
static __device__ float          g_xgF[(size_t)BTR * GG];   // 201 MB
static __device__ float          g_xgR[(size_t)BTR * GG];   // 201 MB
static __device__ unsigned short g_hHi[(size_t)BTR * 256];  // 67 MB (bf16 hi plane)
static __device__ unsigned short g_hLo[(size_t)BTR * 256];  // 67 MB (bf16 lo plane)

// ---------------------------------------------------------------------------
// Helpers
// ---------------------------------------------------------------------------
__device__ __forceinline__ u64 ffma2(u64 a, u64 b, u64 c) {
    u64 d;
    asm("fma.rn.f32x2 %0, %1, %2, %3;" : "=l"(d) : "l"(a), "l"(b), "l"(c));
    return d;
}
__device__ __forceinline__ u64 addf2(u64 a, u64 b) {
    u64 d;
    asm("add.rn.f32x2 %0, %1, %2;" : "=l"(d) : "l"(a), "l"(b));
    return d;
}
__device__ __forceinline__ u64 d2u(double x) {
    return (u64)__double_as_longlong(x);
}
__device__ __forceinline__ float2 unpack2(u64 v) {
    float2 r;
    asm("mov.b64 {%0, %1}, %2;" : "=f"(r.x), "=f"(r.y) : "l"(v));
    return r;
}
__device__ __forceinline__ float sigf(float x) {
    return 1.0f / (1.0f + __expf(-x));
}
__device__ __forceinline__ float tanh_fast(float x) {
    float xc = fminf(fmaxf(x, -20.0f), 20.0f);
    float e  = __expf(-2.0f * xc);
    return (1.0f - e) / (1.0f + e);
}
__device__ __forceinline__ uint32_t smem_u32(const void* p) {
    uint32_t a;
    asm("{ .reg .u64 t; cvta.to.shared.u64 t, %1; cvt.u32.u64 %0, t; }" : "=r"(a) : "l"(p));
    return a;
}

// ---------------------------------------------------------------------------
// Generic fp32 GEMM (K=18 projections): C[M][N] = A[M][K]*B[N][K]^T + bias[N]
// ---------------------------------------------------------------------------
__global__ __launch_bounds__(256) void gemm_tn_bias(
    const float* __restrict__ A, int lda,
    const float* __restrict__ Bw,
    const float* __restrict__ bias,
    float* __restrict__ C, int ldc,
    int M, int N, int K)
{
    const int BM = 64, BN = 64, BK = 16;
    const int PAD = 8;
    __shared__ __align__(16) float As[BK][BM + PAD];
    __shared__ __align__(16) float Bs[BK][BN + PAD];

    int tid = threadIdx.x;
    int tx = tid & 15;
    int ty = tid >> 4;
    int m0 = blockIdx.x * BM;
    int n0 = blockIdx.y * BN;

    float acc[4][4];
#pragma unroll
    for (int i = 0; i < 4; i++)
#pragma unroll
        for (int j = 0; j < 4; j++) acc[i][j] = 0.0f;

    int nkt = (K + BK - 1) / BK;
    for (int kt = 0; kt < nkt; kt++) {
        int k0 = kt * BK;
#pragma unroll
        for (int r = 0; r < 4; r++) {
            int idx = tid + r * 256;
            int m = idx >> 4;
            int k = idx & 15;
            float va = 0.0f, vb = 0.0f;
            if (k0 + k < K) {
                va = A[(size_t)(m0 + m) * lda + k0 + k];
                vb = Bw[(size_t)(n0 + m) * K + k0 + k];
            }
            As[k][m] = va;
            Bs[k][m] = vb;
        }
        __syncthreads();
#pragma unroll
        for (int k = 0; k < BK; k++) {
            float4 a = *(const float4*)&As[k][ty * 4];
            float4 b = *(const float4*)&Bs[k][tx * 4];
            float av[4] = {a.x, a.y, a.z, a.w};
            float bv[4] = {b.x, b.y, b.z, b.w};
#pragma unroll
            for (int i = 0; i < 4; i++)
#pragma unroll
                for (int j = 0; j < 4; j++)
                    acc[i][j] = fmaf(av[i], bv[j], acc[i][j]);
        }
        __syncthreads();
    }

    float4 bv = *(const float4*)&bias[n0 + tx * 4];
#pragma unroll
    for (int i = 0; i < 4; i++) {
        int m = m0 + ty * 4 + i;
        float4 o = make_float4(acc[i][0] + bv.x, acc[i][1] + bv.y,
                               acc[i][2] + bv.z, acc[i][3] + bv.w);
        *(float4*)&C[(size_t)m * ldc + n0 + tx * 4] = o;
    }
}

// ---------------------------------------------------------------------------
// Tensor-core GEMM via mma.sync (K=256): C[BTR][384] = A * W^T + bias
// Fragments hoisted out of term loop: LDSM 24 -> 16 per warp per kk.
// Term order: (Ahi,Whi), (Alo,Whi), (Ahi,Wlo) to minimize live registers.
// ---------------------------------------------------------------------------
#define SA 72
#define SM_PLANE (128 * SA * 2)     // 18432 bytes per plane
__global__ __launch_bounds__(256, 2) void hmma_gemm(
    const unsigned short* __restrict__ Ahi,
    const unsigned short* __restrict__ Alo,
    const float* __restrict__ W,      // [384][256]
    const float* __restrict__ bias,   // [384]
    float* __restrict__ C)            // [BTR][384]
{
    extern __shared__ __align__(16) unsigned short smh[];
    unsigned short* sAhi = smh;
    unsigned short* sAlo = sAhi + 128 * SA;
    unsigned short* sWhi = sAlo + 128 * SA;
    unsigned short* sWlo = sWhi + 128 * SA;

    int tid  = threadIdx.x;
    int lane = tid & 31;
    int warp = tid >> 5;
    size_t m0 = (size_t)blockIdx.x * 128;
    int    n0 = blockIdx.y * 128;
    int m_off = (warp & 1) * 64;
    int n_off = (warp >> 1) * 32;

    float acc[4][4][4];     // [mt][nt][frag]
#pragma unroll
    for (int a = 0; a < 4; a++)
#pragma unroll
        for (int b = 0; b < 4; b++)
#pragma unroll
            for (int c = 0; c < 4; c++) acc[a][b][c] = 0.0f;

    // Loader indices
    int r  = tid >> 1;            // 0..127
    int c0 = (tid & 1) * 32;      // 0 or 32
    const size_t arow = (m0 + r) * GK;
    const size_t wrow = (size_t)(n0 + r) * GK;

    // ldmatrix per-lane address components (element units)
    uint32_t sb = smem_u32(smh);
    int ln  = lane & 7;
    int sel = lane >> 3;
    int aoff = (m_off + ln + (sel & 1) * 8) * SA + (sel >> 1) * 8;
    int half = (lane >> 3) & 1;
    int boff = (n_off + (lane & 7)) * SA + half * 8;

    for (int ch = 0; ch < 4; ch++) {
        int kb = ch * 64 + c0;
        __syncthreads();   // previous chunk's LDSM complete before overwrite

#pragma unroll
        for (int i = 0; i < 4; i++) {
            uint4 va = *(const uint4*)&Ahi[arow + kb + 8 * i];
            *(uint4*)&sAhi[r * SA + c0 + 8 * i] = va;
        }
#pragma unroll
        for (int i = 0; i < 4; i++) {
            uint4 vl = *(const uint4*)&Alo[arow + kb + 8 * i];
            *(uint4*)&sAlo[r * SA + c0 + 8 * i] = vl;
        }
#pragma unroll
        for (int i = 0; i < 8; i++) {
            float4 wv = *(const float4*)&W[wrow + kb + 4 * i];
            __nv_bfloat16 h0 = __float2bfloat16(wv.x);
            __nv_bfloat16 h1 = __float2bfloat16(wv.y);
            __nv_bfloat16 h2 = __float2bfloat16(wv.z);
            __nv_bfloat16 h3 = __float2bfloat16(wv.w);
            __nv_bfloat16 l0 = __float2bfloat16(wv.x - __bfloat162float(h0));
            __nv_bfloat16 l1 = __float2bfloat16(wv.y - __bfloat162float(h1));
            __nv_bfloat16 l2 = __float2bfloat16(wv.z - __bfloat162float(h2));
            __nv_bfloat16 l3 = __float2bfloat16(wv.w - __bfloat162float(h3));
            uint2 uh, ul;
            uh.x = (uint32_t)__bfloat16_as_ushort(h0) | ((uint32_t)__bfloat16_as_ushort(h1) << 16);
            uh.y = (uint32_t)__bfloat16_as_ushort(h2) | ((uint32_t)__bfloat16_as_ushort(h3) << 16);
            ul.x = (uint32_t)__bfloat16_as_ushort(l0) | ((uint32_t)__bfloat16_as_ushort(l1) << 16);
            ul.y = (uint32_t)__bfloat16_as_ushort(l2) | ((uint32_t)__bfloat16_as_ushort(l3) << 16);
            *(uint2*)&sWhi[r * SA + c0 + 4 * i] = uh;
            *(uint2*)&sWlo[r * SA + c0 + 4 * i] = ul;
        }
        __syncthreads();

#pragma unroll
        for (int kk = 0; kk < 4; kk++) {
            uint32_t afh[4][4], afl[4][4], bfr[4][2];
            // Ahi fragments
#pragma unroll
            for (int mt = 0; mt < 4; mt++) {
                uint32_t addr = sb + (uint32_t)(aoff + mt * 16 * SA + kk * 16) * 2;
                asm volatile(
                    "ldmatrix.sync.aligned.m8n8.x4.shared.b16 {%0,%1,%2,%3}, [%4];"
                    : "=r"(afh[mt][0]), "=r"(afh[mt][1]), "=r"(afh[mt][2]), "=r"(afh[mt][3])
                    : "r"(addr));
            }
            // Whi fragments
#pragma unroll
            for (int nt = 0; nt < 4; nt++) {
                uint32_t addr = sb + 2 * SM_PLANE + (uint32_t)(boff + nt * 8 * SA + kk * 16) * 2;
                asm volatile(
                    "ldmatrix.sync.aligned.m8n8.x2.shared.b16 {%0,%1}, [%2];"
                    : "=r"(bfr[nt][0]), "=r"(bfr[nt][1]) : "r"(addr));
            }
            // term: Ahi * Whi
#pragma unroll
            for (int mt = 0; mt < 4; mt++)
#pragma unroll
                for (int nt = 0; nt < 4; nt++)
                    asm volatile(
                        "mma.sync.aligned.m16n8k16.row.col.f32.bf16.bf16.f32 "
                        "{%0,%1,%2,%3}, {%4,%5,%6,%7}, {%8,%9}, {%0,%1,%2,%3};"
                        : "+f"(acc[mt][nt][0]), "+f"(acc[mt][nt][1]),
                          "+f"(acc[mt][nt][2]), "+f"(acc[mt][nt][3])
                        : "r"(afh[mt][0]), "r"(afh[mt][1]), "r"(afh[mt][2]), "r"(afh[mt][3]),
                          "r"(bfr[nt][0]), "r"(bfr[nt][1]));
            // Alo fragments
#pragma unroll
            for (int mt = 0; mt < 4; mt++) {
                uint32_t addr = sb + SM_PLANE + (uint32_t)(aoff + mt * 16 * SA + kk * 16) * 2;
                asm volatile(
                    "ldmatrix.sync.aligned.m8n8.x4.shared.b16 {%0,%1,%2,%3}, [%4];"
                    : "=r"(afl[mt][0]), "=r"(afl[mt][1]), "=r"(afl[mt][2]), "=r"(afl[mt][3])
                    : "r"(addr));
            }
            // term: Alo * Whi (reuses bfr)
#pragma unroll
            for (int mt = 0; mt < 4; mt++)
#pragma unroll
                for (int nt = 0; nt < 4; nt++)
                    asm volatile(
                        "mma.sync.aligned.m16n8k16.row.col.f32.bf16.bf16.f32 "
                        "{%0,%1,%2,%3}, {%4,%5,%6,%7}, {%8,%9}, {%0,%1,%2,%3};"
                        : "+f"(acc[mt][nt][0]), "+f"(acc[mt][nt][1]),
                          "+f"(acc[mt][nt][2]), "+f"(acc[mt][nt][3])
                        : "r"(afl[mt][0]), "r"(afl[mt][1]), "r"(afl[mt][2]), "r"(afl[mt][3]),
                          "r"(bfr[nt][0]), "r"(bfr[nt][1]));
            // Wlo fragments (overwrite bfr; Whi dead)
#pragma unroll
            for (int nt = 0; nt < 4; nt++) {
                uint32_t addr = sb + 3 * SM_PLANE + (uint32_t)(boff + nt * 8 * SA + kk * 16) * 2;
                asm volatile(
                    "ldmatrix.sync.aligned.m8n8.x2.shared.b16 {%0,%1}, [%2];"
                    : "=r"(bfr[nt][0]), "=r"(bfr[nt][1]) : "r"(addr));
            }
            // term: Ahi * Wlo
#pragma unroll
            for (int mt = 0; mt < 4; mt++)
#pragma unroll
                for (int nt = 0; nt < 4; nt++)
                    asm volatile(
                        "mma.sync.aligned.m16n8k16.row.col.f32.bf16.bf16.f32 "
                        "{%0,%1,%2,%3}, {%4,%5,%6,%7}, {%8,%9}, {%0,%1,%2,%3};"
                        : "+f"(acc[mt][nt][0]), "+f"(acc[mt][nt][1]),
                          "+f"(acc[mt][nt][2]), "+f"(acc[mt][nt][3])
                        : "r"(afh[mt][0]), "r"(afh[mt][1]), "r"(afh[mt][2]), "r"(afh[mt][3]),
                          "r"(bfr[nt][0]), "r"(bfr[nt][1]));
        }
    }

    // Epilogue
    int cr  = lane >> 2;
    int cc2 = (lane & 3) * 2;
#pragma unroll
    for (int nt = 0; nt < 4; nt++) {
        int n = n0 + n_off + nt * 8 + cc2;
        float2 bq = *(const float2*)&bias[n];
#pragma unroll
        for (int mt = 0; mt < 4; mt++) {
            size_t m = m0 + m_off + mt * 16 + cr;
            float2 o0 = make_float2(acc[mt][nt][0] + bq.x, acc[mt][nt][1] + bq.y);
            float2 o1 = make_float2(acc[mt][nt][2] + bq.x, acc[mt][nt][3] + bq.y);
            *(float2*)&C[m * GG + n]       = o0;
            *(float2*)&C[(m + 8) * GG + n] = o1;
        }
    }
}

// ---------------------------------------------------------------------------
// GRU scan: role-structured, split named barriers, f32x2 reduction tree.
// grid = 128, 384 threads. g<256: r/z producer; g>=256: n gate + h update.
// Barrier protocol per step:
//   rz-warps:  matvec -> sigma -> store rz -> bar.arrive 1 -> bar.sync 2
//   n-warps:   matvec -> bar.sync 1 -> gate+h write -> bar.arrive 2 -> next
// ---------------------------------------------------------------------------
__global__ __launch_bounds__(384, 1) void gru_scan(
    const float* __restrict__ xgF, const float* __restrict__ xgR,
    const float* __restrict__ whhF, const float* __restrict__ bhhF,
    const float* __restrict__ whhR, const float* __restrict__ bhhR,
    unsigned short* __restrict__ outHi, unsigned short* __restrict__ outLo)
{
    int bb  = blockIdx.x >> 1;
    int dir = blockIdx.x & 1;
    const float* xg  = dir ? xgR  : xgF;
    const float* whh = dir ? whhR : whhF;
    const float* bhh = dir ? bhhR : bhhF;

    int g = threadIdx.x;
    int j = g & 127;

    u64 w2[64];
    {
        const double2* wrow = (const double2*)(whh + (size_t)g * HH);
#pragma unroll
        for (int i = 0; i < 32; i++) {
            double2 v = wrow[i];
            w2[2*i+0] = d2u(v.x);
            w2[2*i+1] = d2u(v.y);
        }
    }
    float bh = bhh[g];

    __shared__ __align__(16) float hs[HH];
    __shared__ float rz[2 * HH];
    if (g < HH) hs[g] = 0.0f;

    const float* xp = xg + (size_t)bb * TT * GG + (size_t)(dir ? (TT - 1) : 0) * GG + g;
    const ptrdiff_t xstep = dir ? -(ptrdiff_t)GG : (ptrdiff_t)GG;

    size_t oidx = (size_t)bb * TT * 256 + (size_t)(dir ? (TT - 1) : 0) * 256
                + (size_t)dir * HH + j;
    const ptrdiff_t ostep = dir ? -(ptrdiff_t)256 : (ptrdiff_t)256;

    float xv = __ldg(xp);
    xp += xstep;
    __syncthreads();

    const double2* hsd = (const double2*)hs;
    bool is_rz = (g < 2 * HH);

    for (int t = 0; t < TT; t++) {
        const float* xpn = (t + 1 < TT) ? xp : (xp - xstep);
        float xv_next = __ldg(xpn);

        u64 a0 = 0ull, a1 = 0ull, a2 = 0ull, a3 = 0ull;
#pragma unroll
        for (int i = 0; i < 16; i++) {
            double2 h0 = hsd[2*i];
            double2 h1 = hsd[2*i+1];
            a0 = ffma2(w2[4*i+0], d2u(h0.x), a0);
            a1 = ffma2(w2[4*i+1], d2u(h0.y), a1);
            a2 = ffma2(w2[4*i+2], d2u(h1.x), a2);
            a3 = ffma2(w2[4*i+3], d2u(h1.y), a3);
        }
        u64 s = addf2(addf2(a0, a1), addf2(a2, a3));
        float2 sp = unpack2(s);
        float acc = sp.x + sp.y + bh;

        if (is_rz) {
            rz[g] = sigf(acc + xv);
            asm volatile("bar.arrive 1, 384;" ::: "memory");
            asm volatile("bar.sync 2, 384;" ::: "memory");
        } else {
            asm volatile("bar.sync 1, 384;" ::: "memory");
            float r  = rz[j];
            float z  = rz[j + HH];
            float n  = tanh_fast(fmaf(r, acc, xv));   // xv = xn here
            float hp = hs[j];
            float hn = fmaf(z, hp - n, n);
            hs[j] = hn;
            __nv_bfloat16 bhi = __float2bfloat16(hn);
            __nv_bfloat16 blo = __float2bfloat16(hn - __bfloat162float(bhi));
            outHi[oidx] = __bfloat16_as_ushort(bhi);
            outLo[oidx] = __bfloat16_as_ushort(blo);
            asm volatile("bar.arrive 2, 384;" ::: "memory");
        }

        xv = xv_next;
        xp += xstep;
        oidx += ostep;
    }
}

// ---------------------------------------------------------------------------
// Final FC: reads h1 = hi + lo planes
// ---------------------------------------------------------------------------
__global__ __launch_bounds__(256) void fc_kernel(
    const unsigned short* __restrict__ hHi,
    const unsigned short* __restrict__ hLo,
    const float* __restrict__ fw,   // [2][256]
    const float* __restrict__ fb,   // [2]
    float* __restrict__ out)        // [rows][2]
{
    int row  = blockIdx.x * 8 + (threadIdx.x >> 5);
    int lane = threadIdx.x & 31;
    size_t base = (size_t)row * 256;
    float a0 = 0.f, a1 = 0.f;
#pragma unroll
    for (int i = 0; i < 8; i++) {
        int k = lane + 32 * i;
        float v = __bfloat162float(__ushort_as_bfloat16(hHi[base + k]))
                + __bfloat162float(__ushort_as_bfloat16(hLo[base + k]));
        a0 = fmaf(v, fw[k],       a0);
        a1 = fmaf(v, fw[256 + k], a1);
    }
#pragma unroll
    for (int off = 16; off; off >>= 1) {
        a0 += __shfl_xor_sync(0xffffffffu, a0, off);
        a1 += __shfl_xor_sync(0xffffffffu, a1, off);
    }
    if (lane == 0) {
        out[(size_t)row * 2 + 0] = a0 + fb[0];
        out[(size_t)row * 2 + 1] = a1 + fb[1];
    }
}

// ---------------------------------------------------------------------------
// Launch
// ---------------------------------------------------------------------------
extern "C" void kernel_launch(void* const* d_in, const int* in_sizes, int n_in,
                              void* d_out, int out_size)
{
    const float* x        = (const float*)d_in[0];
    const float* w_ih_l0  = (const float*)d_in[1];
    const float* w_hh_l0  = (const float*)d_in[2];
    const float* b_ih_l0  = (const float*)d_in[3];
    const float* b_hh_l0  = (const float*)d_in[4];
    const float* w_ih_l0r = (const float*)d_in[5];
    const float* w_hh_l0r = (const float*)d_in[6];
    const float* b_ih_l0r = (const float*)d_in[7];
    const float* b_hh_l0r = (const float*)d_in[8];
    const float* w_ih_l1  = (const float*)d_in[9];
    const float* w_hh_l1  = (const float*)d_in[10];
    const float* b_ih_l1  = (const float*)d_in[11];
    const float* b_hh_l1  = (const float*)d_in[12];
    const float* w_ih_l1r = (const float*)d_in[13];
    const float* w_hh_l1r = (const float*)d_in[14];
    const float* b_ih_l1r = (const float*)d_in[15];
    const float* b_hh_l1r = (const float*)d_in[16];
    const float* fc_w     = (const float*)d_in[17];
    const float* fc_b     = (const float*)d_in[18];
    float* out = (float*)d_out;

    float *xgF, *xgR;
    unsigned short *hHi, *hLo;
    cudaGetSymbolAddress((void**)&xgF, g_xgF);
    cudaGetSymbolAddress((void**)&xgR, g_xgR);
    cudaGetSymbolAddress((void**)&hHi, g_hHi);
    cudaGetSymbolAddress((void**)&hLo, g_hLo);

    static int smem_set = 0;
    const int HM_SMEM = 4 * SM_PLANE;   // 73728 B
    if (!smem_set) {
        cudaFuncSetAttribute(hmma_gemm, cudaFuncAttributeMaxDynamicSharedMemorySize, HM_SMEM);
        smem_set = 1;
    }

    // Layer 0 input projections (K = 18)
    dim3 gGrid(BTR / 64, GG / 64);
    gemm_tn_bias<<<gGrid, 256>>>(x, DIN, w_ih_l0,  b_ih_l0,  xgF, GG, BTR, GG, DIN);
    gemm_tn_bias<<<gGrid, 256>>>(x, DIN, w_ih_l0r, b_ih_l0r, xgR, GG, BTR, GG, DIN);

    // Layer 0 scan -> h0 bf16 hi/lo planes
    gru_scan<<<BB * 2, GG>>>(xgF, xgR, w_hh_l0, b_hh_l0, w_hh_l0r, b_hh_l0r, hHi, hLo);

    // Layer 1 input projections (K = 256): tensor-core GEMM via mma.sync
    dim3 tcGrid(BTR / 128, GG / 128);  // 1024 x 3
    hmma_gemm<<<tcGrid, 256, HM_SMEM>>>(hHi, hLo, w_ih_l1,  b_ih_l1,  xgF);
    hmma_gemm<<<tcGrid, 256, HM_SMEM>>>(hHi, hLo, w_ih_l1r, b_ih_l1r, xgR);

    // Layer 1 scan -> h1 planes
    gru_scan<<<BB * 2, GG>>>(xgF, xgR, w_hh_l1, b_hh_l1, w_hh_l1r, b_hh_l1r, hHi, hLo);

    // Final FC
    fc_kernel<<<BTR / 8, 256>>>(hHi, hLo, fc_w, fc_b, out);
}